// round 15
// baseline (speedup 1.0000x reference)
#include <cuda_runtime.h>
#include <math.h>

#define S_   8192
#define B_   2
#define D_   512
#define H_   2048
#define QK_  128
#define GSZ_ 256
#define KS_  17
#define BS_  (B_*S_)
#define NGRP 32   // S_/GSZ_
#define NSPLIT 8  // split-K for lkvu GEMM

// ---------------- scratch (device globals; no runtime alloc) ----------------
__device__ float g_hstate[BS_*D_];
__device__ float g_nxn[BS_*D_];
__device__ float g_h1[(size_t)BS_*H_];                // GEMM1 out; reused as qvu
__device__ float g_h2[(size_t)BS_*H_];                // [v|u]
__device__ float g_qk1[BS_*QK_];
__device__ float g_qk2[BS_*QK_];
__device__ float g_bqq[BS_*QK_];
__device__ float g_blq[BS_*QK_];
__device__ float g_bkq[BS_*QK_];
__device__ float g_blk[BS_*QK_];
__device__ float g_attn[(size_t)B_*NGRP*GSZ_*GSZ_];
__device__ float g_gate[(size_t)BS_*(2*D_)];
__device__ float g_o1[BS_*D_];
__device__ float g_lkvu[B_*QK_*H_];
__device__ float g_lkvup[(size_t)B_*NSPLIT*QK_*H_];
__device__ float g_ps[BS_];
__device__ float g_ps2[BS_];
__device__ float g_stats[4];

// ---------------- helpers ----------------
__device__ __forceinline__ float blockReduceSum(float v, float* red, int n) {
    int tid = threadIdx.x;
    red[tid] = v; __syncthreads();
    for (int o = n >> 1; o > 0; o >>= 1) {
        if (tid < o) red[tid] += red[tid + o];
        __syncthreads();
    }
    float r = red[0];
    __syncthreads();
    return r;
}

// pack two fp32 (v0 -> low half / even-k, v1 -> high half / odd-k) into bf16x2 hi + lo
__device__ __forceinline__ void packpair(float v0, float v1, unsigned &hi, unsigned &lo) {
    unsigned h;
    asm("cvt.rn.bf16x2.f32 %0, %1, %2;" : "=r"(h) : "f"(v1), "f"(v0));
    float h0 = __uint_as_float(h << 16);
    float h1 = __uint_as_float(h & 0xFFFF0000u);
    float r0 = v0 - h0;
    float r1 = v1 - h1;
    asm("cvt.rn.bf16x2.f32 %0, %1, %2;" : "=r"(lo) : "f"(r1), "f"(r0));
    hi = h;
}

#define MMA_BF16(Cx, A4, B2)                                               \
    asm volatile(                                                          \
        "mma.sync.aligned.m16n8k16.row.col.f32.bf16.bf16.f32 "             \
        "{%0,%1,%2,%3},{%4,%5,%6,%7},{%8,%9},{%0,%1,%2,%3};"               \
        : "+f"(Cx[0]), "+f"(Cx[1]), "+f"(Cx[2]), "+f"(Cx[3])               \
        : "r"(A4[0]), "r"(A4[1]), "r"(A4[2]), "r"(A4[3]),                  \
          "r"(B2[0]), "r"(B2[1]))

// ---------------- 3xBF16 split tensor-core GEMM, pre-split smem ----------------
// (unchanged from R12 — best known: 2 CTAs/SM via __launch_bounds__(256,2))
#define TBM 128
#define TBN 128
#define TBK 16
#define KP  (TBK/2)   // 8 k-pairs
#define SPAD 8
template<int EPI, bool TA, bool TB, bool ACC>
__global__ void __launch_bounds__(256, 2) tgemm_k(
    const float* __restrict__ A, const float* __restrict__ Bm,
    float* __restrict__ C, const float* __restrict__ bias,
    const float* __restrict__ alpha_ptr, float alpha_c,
    int M, int N, int K, int lda, int ldb, int ldc,
    long long sA, long long sB, long long sC, int split)
{
    __shared__ unsigned Ash[2][KP][TBM + SPAD];
    __shared__ unsigned Asl[2][KP][TBM + SPAD];
    __shared__ unsigned Bsh[2][KP][TBN + SPAD];
    __shared__ unsigned Bsl[2][KP][TBN + SPAD];

    const int z = blockIdx.z;
    const int bb = z / split;
    const int sp = z - bb * split;
    A  += (long long)bb * sA + (long long)sp * K * (TA ? (long long)lda : 1LL);
    Bm += (long long)bb * sB + (long long)sp * K * (TB ? 1LL : (long long)ldb);
    C  += (long long)z * sC;

    const int m0 = blockIdx.y * TBM, n0 = blockIdx.x * TBN;
    const int tid = threadIdx.x;
    const int w = tid >> 5, lane = tid & 31;
    const int wm = (w >> 2) * 64, wn = (w & 3) * 32;
    const int r = lane >> 2, c = lane & 3;

    float acc[4][4][4];
    #pragma unroll
    for (int i = 0; i < 4; i++)
        #pragma unroll
        for (int j = 0; j < 4; j++)
            #pragma unroll
            for (int e = 0; e < 4; e++) acc[i][j][e] = 0.f;

    const int nk = K / TBK;
    float4 pa[2], pb[2];

    auto loadA = [&](int kt) {
        #pragma unroll
        for (int i = 0; i < 2; i++) {
            int idx = tid + i * 256;
            if (!TA) {
                int m = idx >> 2, kq = idx & 3;
                pa[i] = *(const float4*)&A[(long long)(m0 + m) * lda + kt * TBK + kq * 4];
            } else {
                int kp = idx >> 6, mp = idx & 63;
                float2 a0 = *(const float2*)&A[(long long)(kt * TBK + 2*kp    ) * lda + m0 + 2*mp];
                float2 a1 = *(const float2*)&A[(long long)(kt * TBK + 2*kp + 1) * lda + m0 + 2*mp];
                pa[i] = make_float4(a0.x, a1.x, a0.y, a1.y);
            }
        }
    };
    auto loadB = [&](int kt) {
        #pragma unroll
        for (int i = 0; i < 2; i++) {
            int idx = tid + i * 256;
            if (TB) {
                int n = idx >> 2, kq = idx & 3;
                pb[i] = *(const float4*)&Bm[(long long)(n0 + n) * ldb + kt * TBK + kq * 4];
            } else {
                int kp = idx >> 6, np = idx & 63;
                float2 b0 = *(const float2*)&Bm[(long long)(kt * TBK + 2*kp    ) * ldb + n0 + 2*np];
                float2 b1 = *(const float2*)&Bm[(long long)(kt * TBK + 2*kp + 1) * ldb + n0 + 2*np];
                pb[i] = make_float4(b0.x, b1.x, b0.y, b1.y);
            }
        }
    };
    auto stsAB = [&](int buf) {
        #pragma unroll
        for (int i = 0; i < 2; i++) {
            int idx = tid + i * 256;
            // ---- A ----
            if (!TA) {
                int m = idx >> 2, kq = idx & 3;
                unsigned h0, l0, h1, l1;
                packpair(pa[i].x, pa[i].y, h0, l0);
                packpair(pa[i].z, pa[i].w, h1, l1);
                Ash[buf][kq*2    ][m] = h0;  Asl[buf][kq*2    ][m] = l0;
                Ash[buf][kq*2 + 1][m] = h1;  Asl[buf][kq*2 + 1][m] = l1;
            } else {
                int kp = idx >> 6, mp = idx & 63;
                unsigned h0, l0, h1, l1;
                packpair(pa[i].x, pa[i].y, h0, l0);   // m = 2mp
                packpair(pa[i].z, pa[i].w, h1, l1);   // m = 2mp+1
                Ash[buf][kp][2*mp] = h0;  Ash[buf][kp][2*mp + 1] = h1;
                Asl[buf][kp][2*mp] = l0;  Asl[buf][kp][2*mp + 1] = l1;
            }
            // ---- B ----
            if (TB) {
                int n = idx >> 2, kq = idx & 3;
                unsigned h0, l0, h1, l1;
                packpair(pb[i].x, pb[i].y, h0, l0);
                packpair(pb[i].z, pb[i].w, h1, l1);
                Bsh[buf][kq*2    ][n] = h0;  Bsl[buf][kq*2    ][n] = l0;
                Bsh[buf][kq*2 + 1][n] = h1;  Bsl[buf][kq*2 + 1][n] = l1;
            } else {
                int kp = idx >> 6, np = idx & 63;
                unsigned h0, l0, h1, l1;
                packpair(pb[i].x, pb[i].y, h0, l0);   // n = 2np
                packpair(pb[i].z, pb[i].w, h1, l1);   // n = 2np+1
                Bsh[buf][kp][2*np] = h0;  Bsh[buf][kp][2*np + 1] = h1;
                Bsl[buf][kp][2*np] = l0;  Bsl[buf][kp][2*np + 1] = l1;
            }
        }
    };

    loadA(0); loadB(0);
    stsAB(0);
    __syncthreads();

    int buf = 0;
    for (int kt = 0; kt < nk; kt++) {
        if (kt + 1 < nk) { loadA(kt + 1); loadB(kt + 1); }

        {
            unsigned ah[4][4], al[4][4], bh[4][2], bl[4][2];
            #pragma unroll
            for (int mf = 0; mf < 4; mf++) {
                int m = wm + mf * 16 + r;
                ah[mf][0] = Ash[buf][c    ][m    ];  al[mf][0] = Asl[buf][c    ][m    ];
                ah[mf][1] = Ash[buf][c    ][m + 8];  al[mf][1] = Asl[buf][c    ][m + 8];
                ah[mf][2] = Ash[buf][c + 4][m    ];  al[mf][2] = Asl[buf][c + 4][m    ];
                ah[mf][3] = Ash[buf][c + 4][m + 8];  al[mf][3] = Asl[buf][c + 4][m + 8];
            }
            #pragma unroll
            for (int nf = 0; nf < 4; nf++) {
                int n = wn + nf * 8 + r;
                bh[nf][0] = Bsh[buf][c    ][n];  bl[nf][0] = Bsl[buf][c    ][n];
                bh[nf][1] = Bsh[buf][c + 4][n];  bl[nf][1] = Bsl[buf][c + 4][n];
            }
            #pragma unroll
            for (int mf = 0; mf < 4; mf++)
                #pragma unroll
                for (int nf = 0; nf < 4; nf++) {
                    MMA_BF16(acc[mf][nf], ah[mf], bh[nf]);
                    MMA_BF16(acc[mf][nf], ah[mf], bl[nf]);
                    MMA_BF16(acc[mf][nf], al[mf], bh[nf]);
                }
        }

        if (kt + 1 < nk) {
            stsAB(buf ^ 1);
            __syncthreads();
            buf ^= 1;
        }
    }

    float alpha = alpha_ptr ? *alpha_ptr : alpha_c;
    #pragma unroll
    for (int mf = 0; mf < 4; mf++) {
        int gm = m0 + wm + mf * 16 + r;
        #pragma unroll
        for (int nf = 0; nf < 4; nf++) {
            int gn = n0 + wn + nf * 8 + c * 2;
            float b0 = 0.f, b1 = 0.f;
            if (EPI == 1) { b0 = bias[gn]; b1 = bias[gn + 1]; }
            #pragma unroll
            for (int half = 0; half < 2; half++) {
                int row = gm + half * 8;
                float v0 = acc[mf][nf][half * 2 + 0] * alpha;
                float v1 = acc[mf][nf][half * 2 + 1] * alpha;
                if (EPI == 1) {
                    v0 += b0; v0 = v0 / (1.f + __expf(-v0));
                    v1 += b1; v1 = v1 / (1.f + __expf(-v1));
                }
                if (EPI == 2) {
                    v0 = fmaxf(v0, 0.f); v0 *= v0;
                    v1 = fmaxf(v1, 0.f); v1 *= v1;
                }
                float2* cp = (float2*)&C[(long long)row * ldc + gn];
                if (ACC) {
                    float2 old = *cp;
                    old.x += v0; old.y += v1;
                    *cp = old;
                } else {
                    float2 nv; nv.x = v0; nv.y = v1;
                    *cp = nv;
                }
            }
        }
    }
}

// ---------------- split-K reduce for lkvu ----------------
__global__ void lkvured_k(const float* __restrict__ part, float* __restrict__ out) {
    long long i = (long long)blockIdx.x * blockDim.x + threadIdx.x;
    const long long per = (long long)QK_ * H_;
    int b = (int)(i / per);
    long long rrem = i - (long long)b * per;
    float s = 0.f;
    #pragma unroll
    for (int sp = 0; sp < NSPLIT; sp++)
        s += part[((long long)(b * NSPLIT + sp)) * per + rrem];
    out[i] = s;
}

// ---------------- transpose x (B,D,S) -> hstate (B,S,D) ----------------
__global__ void transpose_in_k(const float* __restrict__ X, float* __restrict__ Hst) {
    __shared__ float t[32][33];
    int b = blockIdx.z;
    int s0 = blockIdx.x * 32, d0 = blockIdx.y * 32;
    for (int i = threadIdx.y; i < 32; i += 8)
        t[i][threadIdx.x] = X[((long long)b*D_ + d0 + i)*S_ + s0 + threadIdx.x];
    __syncthreads();
    for (int i = threadIdx.y; i < 32; i += 8)
        Hst[((long long)b*S_ + s0 + i)*D_ + d0 + threadIdx.x] = t[threadIdx.x][i];
}

// ---------------- token-shift + scalenorm (g folded as GEMM alpha) --------
__global__ void buildnx_k(const float* __restrict__ Hst, float* __restrict__ NXN) {
    __shared__ float red[128];
    long long row = blockIdx.x;
    int s = (int)(row % S_);
    int tid = threadIdx.x;
    float v[4]; float ss = 0.f;
    #pragma unroll
    for (int j = 0; j < 4; j++) {
        int d = tid + j*128;
        float x;
        if (d < 256) x = (s > 0) ? Hst[(row-1)*D_ + d] : 0.f;
        else         x = Hst[row*D_ + d];
        v[j] = x; ss += x*x;
    }
    ss = blockReduceSum(ss, red, 128);
    float inv = 1.f / fmaxf(sqrtf(ss * (1.f/D_)), 1e-5f);
    #pragma unroll
    for (int j = 0; j < 4; j++)
        NXN[row*D_ + tid + j*128] = v[j]*inv;
}

// ---------------- depthwise conv (same-pad, k=17), float2 channel pairs ----
// Tile: 64 channels x 64 s-outputs, halo 80 rows. Each thread owns one float2
// channel pair and 8 strided outputs -> 2 independent FMA chains (2x ILP),
// half the warp-level LDS (LDS.64, conflict-free). Accumulation order matches
// the scalar version exactly (residual first, taps 0..16) -> bit-identical.
__global__ void __launch_bounds__(256) dwconv_k(
    const float* __restrict__ X, const float* __restrict__ Kw,
    float* __restrict__ Y, float* __restrict__ R, int C, int ADD)
{
    __shared__ float2 sh[80][33];   // 33 float2 stride -> odd word stride, conflict-free
    int c0 = blockIdx.x*64, s0 = blockIdx.y*64, b = blockIdx.z;
    int tid = threadIdx.x;
    const float2* X2 = (const float2*)X;
    const int C2 = C >> 1;
    // load halo: 80 rows x 32 float2, 8 rows per sweep
    for (int i = tid; i < 80*32; i += 256) {
        int rr = i >> 5, cc = i & 31;
        int s = s0 + rr - 8;
        float2 v = make_float2(0.f, 0.f);
        if (s >= 0 && s < S_) v = X2[((long long)b*S_ + s)*C2 + (c0 >> 1) + cc];
        sh[rr][cc] = v;
    }
    __syncthreads();
    int cc = tid & 31;        // float2 channel pair index
    int sg = tid >> 5;        // 8 s-groups
    int ch0 = c0 + 2*cc;
    float2 kr[KS_];
    #pragma unroll
    for (int t = 0; t < KS_; t++) {
        kr[t].x = Kw[ch0*KS_ + t];
        kr[t].y = Kw[(ch0+1)*KS_ + t];
    }
    float2* Y2 = (float2*)Y;
    float2* R2 = (float2*)R;
    #pragma unroll
    for (int j = 0; j < 8; j++) {
        int sl = sg + j*8;    // 0..63
        float2 ctr = sh[sl+8][cc];
        float ax = ctr.x, ay = ctr.y;
        #pragma unroll
        for (int t = 0; t < KS_; t++) {
            float2 wv = sh[sl+t][cc];
            ax = fmaf(wv.x, kr[t].x, ax);
            ay = fmaf(wv.y, kr[t].y, ay);
        }
        long long oi = ((long long)b*S_ + s0 + sl)*C2 + (c0 >> 1) + cc;
        if (ADD) {
            float2 old = R2[oi];
            old.x += ax; old.y += ay;
            R2[oi] = old;
        } else {
            Y2[oi] = make_float2(ax, ay);
        }
    }
}

// ---------------- heads (gamma/beta) + rotary -> 4 buffers ----------------
__global__ void rotary_k(const float* __restrict__ QKin, const float* __restrict__ Gm,
                         const float* __restrict__ Bt,
                         float* __restrict__ OQQ, float* __restrict__ OLQ,
                         float* __restrict__ OKQ, float* __restrict__ OLK) {
    long long row = blockIdx.x;
    int s = (int)(row % S_);
    int d = threadIdx.x;  // 128
    float base = QKin[row*QK_ + d];
    float cc = 1.f, sn = 0.f;
    bool rot = (d < 32);
    if (rot) {
        float invf = powf(10000.f, -(float)(2*(d >> 1)) / 32.f);
        float ang = (float)s * invf;
        sincosf(ang, &sn, &cc);
    }
    float sgn = (d & 1) ? 1.f : -1.f;
    float* outs[4] = {OQQ, OLQ, OKQ, OLK};
    #pragma unroll
    for (int h = 0; h < 4; h++) {
        float t = base*Gm[h*QK_ + d] + Bt[h*QK_ + d];
        float o = t;
        if (rot) {
            float p = __shfl_xor_sync(0xffffffffu, t, 1);
            o = t*cc + sgn*p*sn;
        }
        outs[h][row*QK_ + d] = o;
    }
}

// ---------------- gating + scalenorm over 1024 ------------
__global__ void gating_k(const float* __restrict__ QVU, const float* __restrict__ H2b,
                         const float* __restrict__ gop, float* __restrict__ OUT) {
    __shared__ float red[256];
    long long row = blockIdx.x;
    int tid = threadIdx.x;
    float o[4]; float ss = 0.f;
    #pragma unroll
    for (int j = 0; j < 4; j++) {
        int e = tid + j*256;
        float av = QVU[row*2048 + e];
        float au = QVU[row*2048 + 1024 + e];
        float vv = H2b[row*2048 + e];
        float uu = H2b[row*2048 + 1024 + e];
        float sg = 1.f/(1.f + __expf(-av*uu));
        float val = au * vv * sg;
        o[j] = val; ss += val*val;
    }
    ss = blockReduceSum(ss, red, 256);
    float sc = gop[0] / fmaxf(sqrtf(ss * (1.f/1024.f)), 1e-5f);
    #pragma unroll
    for (int j = 0; j < 4; j++)
        OUT[row*1024 + tid + j*256] = o[j]*sc;
}

// ---------------- final LN over D + groupnorm partials ------------
__global__ void ln_k(const float* __restrict__ Hst, const float* __restrict__ lng,
                     const float* __restrict__ lnb, float* __restrict__ Y,
                     float* __restrict__ PS, float* __restrict__ PS2) {
    __shared__ float red[128];
    long long row = blockIdx.x;
    int tid = threadIdx.x;
    float v[4]; float s = 0.f, s2 = 0.f;
    #pragma unroll
    for (int j = 0; j < 4; j++) {
        float t = Hst[row*D_ + tid + j*128];
        v[j] = t; s += t; s2 += t*t;
    }
    s  = blockReduceSum(s,  red, 128);
    s2 = blockReduceSum(s2, red, 128);
    float mu = s * (1.f/D_);
    float var = s2 * (1.f/D_) - mu*mu;
    float rstd = rsqrtf(var + 1e-6f);
    float ys = 0.f, ys2 = 0.f;
    #pragma unroll
    for (int j = 0; j < 4; j++) {
        int d = tid + j*128;
        float y = (v[j]-mu)*rstd*lng[d] + lnb[d];
        Y[row*D_ + d] = y;
        ys += y; ys2 += y*y;
    }
    ys  = blockReduceSum(ys,  red, 128);
    ys2 = blockReduceSum(ys2, red, 128);
    if (tid == 0) { PS[row] = ys; PS2[row] = ys2; }
}

__global__ void gnred_k(const float* __restrict__ PS, const float* __restrict__ PS2,
                        float* __restrict__ stats) {
    __shared__ double rd[256], rd2[256];
    int b = blockIdx.x, tid = threadIdx.x;
    double s = 0, s2 = 0;
    for (int i = tid; i < S_; i += 256) { s += PS[b*S_+i]; s2 += PS2[b*S_+i]; }
    rd[tid] = s; rd2[tid] = s2; __syncthreads();
    for (int o = 128; o > 0; o >>= 1) {
        if (tid < o) { rd[tid] += rd[tid+o]; rd2[tid] += rd2[tid+o]; }
        __syncthreads();
    }
    if (tid == 0) {
        double n = (double)D_ * (double)S_;
        double m = rd[0] / n;
        double var = rd2[0] / n - m*m;
        stats[b*2]     = (float)m;
        stats[b*2 + 1] = (float)(1.0/sqrt(var + 1e-8));
    }
}

// ---------------- groupnorm apply + transpose + residual ----------------
__global__ void gnapply_k(const float* __restrict__ Y, const float* __restrict__ stats,
                          const float* __restrict__ gw, const float* __restrict__ gb,
                          const float* __restrict__ X, float* __restrict__ O) {
    __shared__ float t[32][33];
    int b = blockIdx.z;
    int s0 = blockIdx.x*32, d0 = blockIdx.y*32;
    for (int i = threadIdx.y; i < 32; i += 8)
        t[i][threadIdx.x] = Y[((long long)b*S_ + s0 + i)*D_ + d0 + threadIdx.x];
    __syncthreads();
    float m = stats[b*2], rstd = stats[b*2 + 1];
    for (int i = threadIdx.y; i < 32; i += 8) {
        int d = d0 + i, s = s0 + threadIdx.x;
        long long oi = ((long long)b*D_ + d)*S_ + s;
        O[oi] = (t[threadIdx.x][i] - m)*rstd*gw[d] + gb[d] + X[oi];
    }
}

// ---------------- host orchestration ----------------
extern "C" void kernel_launch(void* const* d_in, const int* in_sizes, int n_in,
                              void* d_out, int out_size)
{
    const float* x      = (const float*)d_in[0];
    const float* g_hid  = (const float*)d_in[1];
    const float* W_hid  = (const float*)d_in[2];
    const float* b_hid  = (const float*)d_in[3];
    const float* k_hid  = (const float*)d_in[4];
    const float* g_qkp  = (const float*)d_in[5];
    const float* W_qkp  = (const float*)d_in[6];
    const float* b_qkp  = (const float*)d_in[7];
    const float* k_qkp  = (const float*)d_in[8];
    const float* g_outp = (const float*)d_in[9];
    const float* W_outp = (const float*)d_in[10];
    const float* b_outp = (const float*)d_in[11];
    const float* k_outp = (const float*)d_in[12];
    const float* gamma  = (const float*)d_in[13];
    const float* beta   = (const float*)d_in[14];
    const float* ln_g   = (const float*)d_in[15];
    const float* ln_b   = (const float*)d_in[16];
    const float* gn_w   = (const float*)d_in[17];
    const float* gn_b   = (const float*)d_in[18];
    float* out = (float*)d_out;

    float *hstate,*nxn,*h1,*h2,*qk1,*qk2,*bqq,*blq,*bkq,*blk,*attn,*gate,*o1,*lkvu,*lkvup,*ps,*ps2,*stats;
    cudaGetSymbolAddress((void**)&hstate, g_hstate);
    cudaGetSymbolAddress((void**)&nxn,    g_nxn);
    cudaGetSymbolAddress((void**)&h1,     g_h1);
    cudaGetSymbolAddress((void**)&h2,     g_h2);
    cudaGetSymbolAddress((void**)&qk1,    g_qk1);
    cudaGetSymbolAddress((void**)&qk2,    g_qk2);
    cudaGetSymbolAddress((void**)&bqq,    g_bqq);
    cudaGetSymbolAddress((void**)&blq,    g_blq);
    cudaGetSymbolAddress((void**)&bkq,    g_bkq);
    cudaGetSymbolAddress((void**)&blk,    g_blk);
    cudaGetSymbolAddress((void**)&attn,   g_attn);
    cudaGetSymbolAddress((void**)&gate,   g_gate);
    cudaGetSymbolAddress((void**)&o1,     g_o1);
    cudaGetSymbolAddress((void**)&lkvu,   g_lkvu);
    cudaGetSymbolAddress((void**)&lkvup,  g_lkvup);
    cudaGetSymbolAddress((void**)&ps,     g_ps);
    cudaGetSymbolAddress((void**)&ps2,    g_ps2);
    cudaGetSymbolAddress((void**)&stats,  g_stats);

    transpose_in_k<<<dim3(S_/32, D_/32, B_), dim3(32, 8)>>>(x, hstate);

    for (int l = 0; l < 2; l++) {
        const float* Wh = W_hid  + (size_t)l*D_*H_;
        const float* bh = b_hid  + l*H_;
        const float* kh = k_hid  + (size_t)l*H_*KS_;
        const float* Wq = W_qkp  + (size_t)l*D_*QK_;
        const float* bq = b_qkp  + l*QK_;
        const float* kq = k_qkp  + (size_t)l*QK_*KS_;
        const float* Wo = W_outp + (size_t)l*2*D_*D_;
        const float* bo = b_outp + l*D_;
        const float* ko = k_outp + (size_t)l*D_*KS_;
        const float* gm = gamma  + l*4*QK_;
        const float* bt = beta   + l*4*QK_;

        // nx (token shift) + scalenorm
        buildnx_k<<<BS_, 128>>>(hstate, nxn);

        // h1 = silu(g_hid * nxn @ Wh + bh)   [16384,2048,512]
        tgemm_k<1,false,false,false><<<dim3(H_/TBN, BS_/TBM, 1), 256>>>(
            nxn, Wh, h1, bh, g_hid + l, 1.f,
            BS_, H_, D_, D_, H_, H_, 0, 0, 0, 1);
        // h2 = h1 + dwconv(h1)
        dwconv_k<<<dim3(H_/64, S_/64, B_), 256>>>(h1, kh, h2, nullptr, H_, 0);

        // qk = silu(g_qk * nxn @ Wq + bq)    [16384,128,512]
        tgemm_k<1,false,false,false><<<dim3(QK_/TBN, BS_/TBM, 1), 256>>>(
            nxn, Wq, qk1, bq, g_qkp + l, 1.f,
            BS_, QK_, D_, D_, QK_, QK_, 0, 0, 0, 1);
        dwconv_k<<<dim3(QK_/64, S_/64, B_), 256>>>(qk1, kq, qk2, nullptr, QK_, 0);
        rotary_k<<<BS_, 128>>>(qk2, gm, bt, bqq, blq, bkq, blk);

        // attn = relu(qq@qk^T / 256)^2       batched 64 x [256,256,128]
        tgemm_k<2,false,true,false><<<dim3(GSZ_/TBN, GSZ_/TBM, B_*NGRP), 256>>>(
            bqq, bkq, attn, nullptr, nullptr, 1.f/(float)GSZ_,
            GSZ_, GSZ_, QK_, QK_, QK_, GSZ_,
            (long long)GSZ_*QK_, (long long)GSZ_*QK_, (long long)GSZ_*GSZ_, 1);

        // qvu = attn @ h2_group              batched 64 x [256,2048,256]
        tgemm_k<0,false,false,false><<<dim3(H_/TBN, GSZ_/TBM, B_*NGRP), 256>>>(
            attn, h2, h1, nullptr, nullptr, 1.f,
            GSZ_, H_, GSZ_, GSZ_, H_, H_,
            (long long)GSZ_*GSZ_, (long long)GSZ_*H_, (long long)GSZ_*H_, 1);

        // lkvu partials = lk^T @ h2 / S      split-K=8, batch 2 -> z=16
        tgemm_k<0,true,false,false><<<dim3(H_/TBN, QK_/TBM, B_*NSPLIT), 256>>>(
            blk, h2, lkvup, nullptr, nullptr, 1.f/(float)S_,
            QK_, H_, S_/NSPLIT, QK_, H_, H_,
            (long long)S_*QK_, (long long)S_*H_, (long long)QK_*H_, NSPLIT);
        lkvured_k<<<(B_*QK_*H_)/256, 256>>>(lkvup, lkvu);

        // qvu += lq @ lkvu                   batch 2 x [8192,2048,128]
        tgemm_k<0,false,false,true><<<dim3(H_/TBN, S_/TBM, B_), 256>>>(
            blq, lkvu, h1, nullptr, nullptr, 1.f,
            S_, H_, QK_, QK_, H_, H_,
            (long long)S_*QK_, (long long)QK_*H_, (long long)S_*H_, 1);

        // gated output + scalenorm (g_out folded)
        gating_k<<<BS_, 256>>>(h1, h2, g_outp + l, gate);

        // o1 = silu(gate @ Wo + bo)          [16384,512,1024]
        tgemm_k<1,false,false,false><<<dim3(D_/TBN, BS_/TBM, 1), 256>>>(
            gate, Wo, o1, bo, nullptr, 1.f,
            BS_, D_, 2*D_, 2*D_, D_, D_, 0, 0, 0, 1);

        // hstate += o1 + dwconv(o1)
        dwconv_k<<<dim3(D_/64, S_/64, B_), 256>>>(o1, ko, nullptr, hstate, D_, 1);
    }

    ln_k<<<BS_, 128>>>(hstate, ln_g, ln_b, nxn, ps, ps2);
    gnred_k<<<B_, 256>>>(ps, ps2, stats);
    gnapply_k<<<dim3(S_/32, D_/32, B_), dim3(32, 8)>>>(nxn, stats, gn_w, gn_b, x, out);
}

// round 16
// speedup vs baseline: 1.0159x; 1.0159x over previous
#include <cuda_runtime.h>
#include <math.h>

#define S_   8192
#define B_   2
#define D_   512
#define H_   2048
#define QK_  128
#define NCAT (H_ + QK_)   // 2176 merged h|qk width
#define GSZ_ 256
#define KS_  17
#define BS_  (B_*S_)
#define NGRP 32   // S_/GSZ_
#define NSPLIT 8  // split-K for lkvu GEMM

// ---------------- scratch (device globals; no runtime alloc) ----------------
__device__ float g_hstate[BS_*D_];
__device__ float g_nxn[BS_*D_];
__device__ float g_hq[(size_t)BS_*NCAT];              // merged GEMM out [h1|qk1]
__device__ float g_h1[(size_t)BS_*H_];                // qvu
__device__ float g_h2[(size_t)BS_*H_];                // [v|u]
__device__ float g_qk2[BS_*QK_];
__device__ float g_bqq[BS_*QK_];
__device__ float g_blq[BS_*QK_];
__device__ float g_bkq[BS_*QK_];
__device__ float g_blk[BS_*QK_];
__device__ float g_attn[(size_t)B_*NGRP*GSZ_*GSZ_];
__device__ float g_gate[(size_t)BS_*(2*D_)];
__device__ float g_o1[BS_*D_];
__device__ float g_lkvu[B_*QK_*H_];
__device__ float g_lkvup[(size_t)B_*NSPLIT*QK_*H_];
__device__ float g_wcat[D_*NCAT];
__device__ float g_bcat[NCAT];
__device__ float g_ps[BS_];
__device__ float g_ps2[BS_];
__device__ float g_stats[4];

// ---------------- helpers ----------------
__device__ __forceinline__ float blockReduceSum(float v, float* red, int n) {
    int tid = threadIdx.x;
    red[tid] = v; __syncthreads();
    for (int o = n >> 1; o > 0; o >>= 1) {
        if (tid < o) red[tid] += red[tid + o];
        __syncthreads();
    }
    float r = red[0];
    __syncthreads();
    return r;
}

// pack two fp32 (v0 -> low half / even-k, v1 -> high half / odd-k) into bf16x2 hi + lo
__device__ __forceinline__ void packpair(float v0, float v1, unsigned &hi, unsigned &lo) {
    unsigned h;
    asm("cvt.rn.bf16x2.f32 %0, %1, %2;" : "=r"(h) : "f"(v1), "f"(v0));
    float h0 = __uint_as_float(h << 16);
    float h1 = __uint_as_float(h & 0xFFFF0000u);
    float r0 = v0 - h0;
    float r1 = v1 - h1;
    asm("cvt.rn.bf16x2.f32 %0, %1, %2;" : "=r"(lo) : "f"(r1), "f"(r0));
    hi = h;
}

#define MMA_BF16(Cx, A4, B2)                                               \
    asm volatile(                                                          \
        "mma.sync.aligned.m16n8k16.row.col.f32.bf16.bf16.f32 "             \
        "{%0,%1,%2,%3},{%4,%5,%6,%7},{%8,%9},{%0,%1,%2,%3};"               \
        : "+f"(Cx[0]), "+f"(Cx[1]), "+f"(Cx[2]), "+f"(Cx[3])               \
        : "r"(A4[0]), "r"(A4[1]), "r"(A4[2]), "r"(A4[3]),                  \
          "r"(B2[0]), "r"(B2[1]))

// ---------------- 3xBF16 split tensor-core GEMM, pre-split smem ----------------
// (R12 best-known: 2 CTAs/SM via __launch_bounds__(256,2))
#define TBM 128
#define TBN 128
#define TBK 16
#define KP  (TBK/2)   // 8 k-pairs
#define SPAD 8
template<int EPI, bool TA, bool TB, bool ACC>
__global__ void __launch_bounds__(256, 2) tgemm_k(
    const float* __restrict__ A, const float* __restrict__ Bm,
    float* __restrict__ C, const float* __restrict__ bias,
    const float* __restrict__ alpha_ptr, float alpha_c,
    int M, int N, int K, int lda, int ldb, int ldc,
    long long sA, long long sB, long long sC, int split)
{
    __shared__ unsigned Ash[2][KP][TBM + SPAD];
    __shared__ unsigned Asl[2][KP][TBM + SPAD];
    __shared__ unsigned Bsh[2][KP][TBN + SPAD];
    __shared__ unsigned Bsl[2][KP][TBN + SPAD];

    const int z = blockIdx.z;
    const int bb = z / split;
    const int sp = z - bb * split;
    A  += (long long)bb * sA + (long long)sp * K * (TA ? (long long)lda : 1LL);
    Bm += (long long)bb * sB + (long long)sp * K * (TB ? 1LL : (long long)ldb);
    C  += (long long)z * sC;

    const int m0 = blockIdx.y * TBM, n0 = blockIdx.x * TBN;
    const int tid = threadIdx.x;
    const int w = tid >> 5, lane = tid & 31;
    const int wm = (w >> 2) * 64, wn = (w & 3) * 32;
    const int r = lane >> 2, c = lane & 3;

    float acc[4][4][4];
    #pragma unroll
    for (int i = 0; i < 4; i++)
        #pragma unroll
        for (int j = 0; j < 4; j++)
            #pragma unroll
            for (int e = 0; e < 4; e++) acc[i][j][e] = 0.f;

    const int nk = K / TBK;
    float4 pa[2], pb[2];

    auto loadA = [&](int kt) {
        #pragma unroll
        for (int i = 0; i < 2; i++) {
            int idx = tid + i * 256;
            if (!TA) {
                int m = idx >> 2, kq = idx & 3;
                pa[i] = *(const float4*)&A[(long long)(m0 + m) * lda + kt * TBK + kq * 4];
            } else {
                int kp = idx >> 6, mp = idx & 63;
                float2 a0 = *(const float2*)&A[(long long)(kt * TBK + 2*kp    ) * lda + m0 + 2*mp];
                float2 a1 = *(const float2*)&A[(long long)(kt * TBK + 2*kp + 1) * lda + m0 + 2*mp];
                pa[i] = make_float4(a0.x, a1.x, a0.y, a1.y);
            }
        }
    };
    auto loadB = [&](int kt) {
        #pragma unroll
        for (int i = 0; i < 2; i++) {
            int idx = tid + i * 256;
            if (TB) {
                int n = idx >> 2, kq = idx & 3;
                pb[i] = *(const float4*)&Bm[(long long)(n0 + n) * ldb + kt * TBK + kq * 4];
            } else {
                int kp = idx >> 6, np = idx & 63;
                float2 b0 = *(const float2*)&Bm[(long long)(kt * TBK + 2*kp    ) * ldb + n0 + 2*np];
                float2 b1 = *(const float2*)&Bm[(long long)(kt * TBK + 2*kp + 1) * ldb + n0 + 2*np];
                pb[i] = make_float4(b0.x, b1.x, b0.y, b1.y);
            }
        }
    };
    auto stsAB = [&](int buf) {
        #pragma unroll
        for (int i = 0; i < 2; i++) {
            int idx = tid + i * 256;
            // ---- A ----
            if (!TA) {
                int m = idx >> 2, kq = idx & 3;
                unsigned h0, l0, h1, l1;
                packpair(pa[i].x, pa[i].y, h0, l0);
                packpair(pa[i].z, pa[i].w, h1, l1);
                Ash[buf][kq*2    ][m] = h0;  Asl[buf][kq*2    ][m] = l0;
                Ash[buf][kq*2 + 1][m] = h1;  Asl[buf][kq*2 + 1][m] = l1;
            } else {
                int kp = idx >> 6, mp = idx & 63;
                unsigned h0, l0, h1, l1;
                packpair(pa[i].x, pa[i].y, h0, l0);   // m = 2mp
                packpair(pa[i].z, pa[i].w, h1, l1);   // m = 2mp+1
                Ash[buf][kp][2*mp] = h0;  Ash[buf][kp][2*mp + 1] = h1;
                Asl[buf][kp][2*mp] = l0;  Asl[buf][kp][2*mp + 1] = l1;
            }
            // ---- B ----
            if (TB) {
                int n = idx >> 2, kq = idx & 3;
                unsigned h0, l0, h1, l1;
                packpair(pb[i].x, pb[i].y, h0, l0);
                packpair(pb[i].z, pb[i].w, h1, l1);
                Bsh[buf][kq*2    ][n] = h0;  Bsl[buf][kq*2    ][n] = l0;
                Bsh[buf][kq*2 + 1][n] = h1;  Bsl[buf][kq*2 + 1][n] = l1;
            } else {
                int kp = idx >> 6, np = idx & 63;
                unsigned h0, l0, h1, l1;
                packpair(pb[i].x, pb[i].y, h0, l0);   // n = 2np
                packpair(pb[i].z, pb[i].w, h1, l1);   // n = 2np+1
                Bsh[buf][kp][2*np] = h0;  Bsh[buf][kp][2*np + 1] = h1;
                Bsl[buf][kp][2*np] = l0;  Bsl[buf][kp][2*np + 1] = l1;
            }
        }
    };

    loadA(0); loadB(0);
    stsAB(0);
    __syncthreads();

    int buf = 0;
    for (int kt = 0; kt < nk; kt++) {
        if (kt + 1 < nk) { loadA(kt + 1); loadB(kt + 1); }

        {
            unsigned ah[4][4], al[4][4], bh[4][2], bl[4][2];
            #pragma unroll
            for (int mf = 0; mf < 4; mf++) {
                int m = wm + mf * 16 + r;
                ah[mf][0] = Ash[buf][c    ][m    ];  al[mf][0] = Asl[buf][c    ][m    ];
                ah[mf][1] = Ash[buf][c    ][m + 8];  al[mf][1] = Asl[buf][c    ][m + 8];
                ah[mf][2] = Ash[buf][c + 4][m    ];  al[mf][2] = Asl[buf][c + 4][m    ];
                ah[mf][3] = Ash[buf][c + 4][m + 8];  al[mf][3] = Asl[buf][c + 4][m + 8];
            }
            #pragma unroll
            for (int nf = 0; nf < 4; nf++) {
                int n = wn + nf * 8 + r;
                bh[nf][0] = Bsh[buf][c    ][n];  bl[nf][0] = Bsl[buf][c    ][n];
                bh[nf][1] = Bsh[buf][c + 4][n];  bl[nf][1] = Bsl[buf][c + 4][n];
            }
            #pragma unroll
            for (int mf = 0; mf < 4; mf++)
                #pragma unroll
                for (int nf = 0; nf < 4; nf++) {
                    MMA_BF16(acc[mf][nf], ah[mf], bh[nf]);
                    MMA_BF16(acc[mf][nf], ah[mf], bl[nf]);
                    MMA_BF16(acc[mf][nf], al[mf], bh[nf]);
                }
        }

        if (kt + 1 < nk) {
            stsAB(buf ^ 1);
            __syncthreads();
            buf ^= 1;
        }
    }

    float alpha = alpha_ptr ? *alpha_ptr : alpha_c;
    #pragma unroll
    for (int mf = 0; mf < 4; mf++) {
        int gm = m0 + wm + mf * 16 + r;
        #pragma unroll
        for (int nf = 0; nf < 4; nf++) {
            int gn = n0 + wn + nf * 8 + c * 2;
            float b0 = 0.f, b1 = 0.f;
            if (EPI == 1) { b0 = bias[gn]; b1 = bias[gn + 1]; }
            #pragma unroll
            for (int half = 0; half < 2; half++) {
                int row = gm + half * 8;
                float v0 = acc[mf][nf][half * 2 + 0] * alpha;
                float v1 = acc[mf][nf][half * 2 + 1] * alpha;
                if (EPI == 1) {
                    v0 += b0; v0 = v0 / (1.f + __expf(-v0));
                    v1 += b1; v1 = v1 / (1.f + __expf(-v1));
                }
                if (EPI == 2) {
                    v0 = fmaxf(v0, 0.f); v0 *= v0;
                    v1 = fmaxf(v1, 0.f); v1 *= v1;
                }
                float2* cp = (float2*)&C[(long long)row * ldc + gn];
                if (ACC) {
                    float2 old = *cp;
                    old.x += v0; old.y += v1;
                    *cp = old;
                } else {
                    float2 nv; nv.x = v0; nv.y = v1;
                    *cp = nv;
                }
            }
        }
    }
}

// ---------------- weight concat + g-fold: Wc = [Wh*gh | Wq*gq], bc = [bh | bq] ----
__global__ void wcat_k(const float* __restrict__ Wh, const float* __restrict__ Wq,
                       const float* __restrict__ bh, const float* __restrict__ bq,
                       const float* __restrict__ gh, const float* __restrict__ gq,
                       float* __restrict__ Wc, float* __restrict__ bc) {
    int idx = blockIdx.x * 256 + threadIdx.x;   // over D_*NCAT
    if (idx >= D_ * NCAT) return;
    int k = idx / NCAT, n = idx - k * NCAT;
    float v;
    if (n < H_) v = Wh[k * H_ + n] * gh[0];
    else        v = Wq[k * QK_ + (n - H_)] * gq[0];
    Wc[idx] = v;
    if (idx < NCAT) bc[idx] = (idx < H_) ? bh[idx] : bq[idx - H_];
}

// ---------------- split-K reduce for lkvu ----------------
__global__ void lkvured_k(const float* __restrict__ part, float* __restrict__ out) {
    long long i = (long long)blockIdx.x * blockDim.x + threadIdx.x;
    const long long per = (long long)QK_ * H_;
    int b = (int)(i / per);
    long long rrem = i - (long long)b * per;
    float s = 0.f;
    #pragma unroll
    for (int sp = 0; sp < NSPLIT; sp++)
        s += part[((long long)(b * NSPLIT + sp)) * per + rrem];
    out[i] = s;
}

// ---------------- transpose x (B,D,S) -> hstate (B,S,D) ----------------
__global__ void transpose_in_k(const float* __restrict__ X, float* __restrict__ Hst) {
    __shared__ float t[32][33];
    int b = blockIdx.z;
    int s0 = blockIdx.x * 32, d0 = blockIdx.y * 32;
    for (int i = threadIdx.y; i < 32; i += 8)
        t[i][threadIdx.x] = X[((long long)b*D_ + d0 + i)*S_ + s0 + threadIdx.x];
    __syncthreads();
    for (int i = threadIdx.y; i < 32; i += 8)
        Hst[((long long)b*S_ + s0 + i)*D_ + d0 + threadIdx.x] = t[threadIdx.x][i];
}

// ---------------- token-shift + scalenorm (g folded into weights) --------
__global__ void buildnx_k(const float* __restrict__ Hst, float* __restrict__ NXN) {
    __shared__ float red[128];
    long long row = blockIdx.x;
    int s = (int)(row % S_);
    int tid = threadIdx.x;
    float v[4]; float ss = 0.f;
    #pragma unroll
    for (int j = 0; j < 4; j++) {
        int d = tid + j*128;
        float x;
        if (d < 256) x = (s > 0) ? Hst[(row-1)*D_ + d] : 0.f;
        else         x = Hst[row*D_ + d];
        v[j] = x; ss += x*x;
    }
    ss = blockReduceSum(ss, red, 128);
    float inv = 1.f / fmaxf(sqrtf(ss * (1.f/D_)), 1e-5f);
    #pragma unroll
    for (int j = 0; j < 4; j++)
        NXN[row*D_ + tid + j*128] = v[j]*inv;
}

// ---------------- depthwise conv (same-pad, k=17) — R4 best-measured form ----
// block: 32 channels x 64 s; smem halo 80x32 + taps in smem; strided outputs.
// ldin = input row stride (supports reading a column slice of the merged hq).
__global__ void __launch_bounds__(256) dwconv_k(
    const float* __restrict__ X, const float* __restrict__ Kw,
    float* __restrict__ Y, float* __restrict__ R, int C, int ldin, int ADD)
{
    __shared__ float sh[80][32];
    __shared__ float sk[32][KS_];
    int c0 = blockIdx.x*32, s0 = blockIdx.y*64, b = blockIdx.z;
    int tid = threadIdx.x;
    for (int i = tid; i < 80*32; i += 256) {
        int rr = i >> 5, cc = i & 31;
        int s = s0 + rr - 8;
        float v = 0.f;
        if (s >= 0 && s < S_) v = X[((long long)b*S_ + s)*ldin + c0 + cc];
        sh[rr][cc] = v;
    }
    for (int i = tid; i < 32*KS_; i += 256) {
        int cc = i / KS_, t = i - cc*KS_;
        sk[cc][t] = Kw[(c0+cc)*KS_ + t];
    }
    __syncthreads();
    #pragma unroll
    for (int j = 0; j < 8; j++) {
        int idx = tid + j*256;
        int sl = idx >> 5, cc = idx & 31;
        float acc = sh[sl+8][cc];
        #pragma unroll
        for (int t = 0; t < KS_; t++) acc = fmaf(sh[sl+t][cc], sk[cc][t], acc);
        long long oi = ((long long)b*S_ + s0 + sl)*C + c0 + cc;
        if (ADD) R[oi] += acc; else Y[oi] = acc;
    }
}

// ---------------- heads (gamma/beta) + rotary -> 4 buffers ----------------
__global__ void rotary_k(const float* __restrict__ QKin, const float* __restrict__ Gm,
                         const float* __restrict__ Bt,
                         float* __restrict__ OQQ, float* __restrict__ OLQ,
                         float* __restrict__ OKQ, float* __restrict__ OLK) {
    long long row = blockIdx.x;
    int s = (int)(row % S_);
    int d = threadIdx.x;  // 128
    float base = QKin[row*QK_ + d];
    float cc = 1.f, sn = 0.f;
    bool rot = (d < 32);
    if (rot) {
        float invf = powf(10000.f, -(float)(2*(d >> 1)) / 32.f);
        float ang = (float)s * invf;
        sincosf(ang, &sn, &cc);
    }
    float sgn = (d & 1) ? 1.f : -1.f;
    float* outs[4] = {OQQ, OLQ, OKQ, OLK};
    #pragma unroll
    for (int h = 0; h < 4; h++) {
        float t = base*Gm[h*QK_ + d] + Bt[h*QK_ + d];
        float o = t;
        if (rot) {
            float p = __shfl_xor_sync(0xffffffffu, t, 1);
            o = t*cc + sgn*p*sn;
        }
        outs[h][row*QK_ + d] = o;
    }
}

// ---------------- gating + scalenorm over 1024 ------------
__global__ void gating_k(const float* __restrict__ QVU, const float* __restrict__ H2b,
                         const float* __restrict__ gop, float* __restrict__ OUT) {
    __shared__ float red[256];
    long long row = blockIdx.x;
    int tid = threadIdx.x;
    float o[4]; float ss = 0.f;
    #pragma unroll
    for (int j = 0; j < 4; j++) {
        int e = tid + j*256;
        float av = QVU[row*2048 + e];
        float au = QVU[row*2048 + 1024 + e];
        float vv = H2b[row*2048 + e];
        float uu = H2b[row*2048 + 1024 + e];
        float sg = 1.f/(1.f + __expf(-av*uu));
        float val = au * vv * sg;
        o[j] = val; ss += val*val;
    }
    ss = blockReduceSum(ss, red, 256);
    float sc = gop[0] / fmaxf(sqrtf(ss * (1.f/1024.f)), 1e-5f);
    #pragma unroll
    for (int j = 0; j < 4; j++)
        OUT[row*1024 + tid + j*256] = o[j]*sc;
}

// ---------------- final LN over D + groupnorm partials ------------
__global__ void ln_k(const float* __restrict__ Hst, const float* __restrict__ lng,
                     const float* __restrict__ lnb, float* __restrict__ Y,
                     float* __restrict__ PS, float* __restrict__ PS2) {
    __shared__ float red[128];
    long long row = blockIdx.x;
    int tid = threadIdx.x;
    float v[4]; float s = 0.f, s2 = 0.f;
    #pragma unroll
    for (int j = 0; j < 4; j++) {
        float t = Hst[row*D_ + tid + j*128];
        v[j] = t; s += t; s2 += t*t;
    }
    s  = blockReduceSum(s,  red, 128);
    s2 = blockReduceSum(s2, red, 128);
    float mu = s * (1.f/D_);
    float var = s2 * (1.f/D_) - mu*mu;
    float rstd = rsqrtf(var + 1e-6f);
    float ys = 0.f, ys2 = 0.f;
    #pragma unroll
    for (int j = 0; j < 4; j++) {
        int d = tid + j*128;
        float y = (v[j]-mu)*rstd*lng[d] + lnb[d];
        Y[row*D_ + d] = y;
        ys += y; ys2 += y*y;
    }
    ys  = blockReduceSum(ys,  red, 128);
    ys2 = blockReduceSum(ys2, red, 128);
    if (tid == 0) { PS[row] = ys; PS2[row] = ys2; }
}

__global__ void gnred_k(const float* __restrict__ PS, const float* __restrict__ PS2,
                        float* __restrict__ stats) {
    __shared__ double rd[256], rd2[256];
    int b = blockIdx.x, tid = threadIdx.x;
    double s = 0, s2 = 0;
    for (int i = tid; i < S_; i += 256) { s += PS[b*S_+i]; s2 += PS2[b*S_+i]; }
    rd[tid] = s; rd2[tid] = s2; __syncthreads();
    for (int o = 128; o > 0; o >>= 1) {
        if (tid < o) { rd[tid] += rd[tid+o]; rd2[tid] += rd2[tid+o]; }
        __syncthreads();
    }
    if (tid == 0) {
        double n = (double)D_ * (double)S_;
        double m = rd[0] / n;
        double var = rd2[0] / n - m*m;
        stats[b*2]     = (float)m;
        stats[b*2 + 1] = (float)(1.0/sqrt(var + 1e-8));
    }
}

// ---------------- groupnorm apply + transpose + residual ----------------
__global__ void gnapply_k(const float* __restrict__ Y, const float* __restrict__ stats,
                          const float* __restrict__ gw, const float* __restrict__ gb,
                          const float* __restrict__ X, float* __restrict__ O) {
    __shared__ float t[32][33];
    int b = blockIdx.z;
    int s0 = blockIdx.x*32, d0 = blockIdx.y*32;
    for (int i = threadIdx.y; i < 32; i += 8)
        t[i][threadIdx.x] = Y[((long long)b*S_ + s0 + i)*D_ + d0 + threadIdx.x];
    __syncthreads();
    float m = stats[b*2], rstd = stats[b*2 + 1];
    for (int i = threadIdx.y; i < 32; i += 8) {
        int d = d0 + i, s = s0 + threadIdx.x;
        long long oi = ((long long)b*D_ + d)*S_ + s;
        O[oi] = (t[threadIdx.x][i] - m)*rstd*gw[d] + gb[d] + X[oi];
    }
}

// ---------------- host orchestration ----------------
extern "C" void kernel_launch(void* const* d_in, const int* in_sizes, int n_in,
                              void* d_out, int out_size)
{
    const float* x      = (const float*)d_in[0];
    const float* g_hid  = (const float*)d_in[1];
    const float* W_hid  = (const float*)d_in[2];
    const float* b_hid  = (const float*)d_in[3];
    const float* k_hid  = (const float*)d_in[4];
    const float* g_qkp  = (const float*)d_in[5];
    const float* W_qkp  = (const float*)d_in[6];
    const float* b_qkp  = (const float*)d_in[7];
    const float* k_qkp  = (const float*)d_in[8];
    const float* g_outp = (const float*)d_in[9];
    const float* W_outp = (const float*)d_in[10];
    const float* b_outp = (const float*)d_in[11];
    const float* k_outp = (const float*)d_in[12];
    const float* gamma  = (const float*)d_in[13];
    const float* beta   = (const float*)d_in[14];
    const float* ln_g   = (const float*)d_in[15];
    const float* ln_b   = (const float*)d_in[16];
    const float* gn_w   = (const float*)d_in[17];
    const float* gn_b   = (const float*)d_in[18];
    float* out = (float*)d_out;

    float *hstate,*nxn,*hq,*h1,*h2,*qk2,*bqq,*blq,*bkq,*blk,*attn,*gate,*o1,*lkvu,*lkvup,*wcat,*bcat,*ps,*ps2,*stats;
    cudaGetSymbolAddress((void**)&hstate, g_hstate);
    cudaGetSymbolAddress((void**)&nxn,    g_nxn);
    cudaGetSymbolAddress((void**)&hq,     g_hq);
    cudaGetSymbolAddress((void**)&h1,     g_h1);
    cudaGetSymbolAddress((void**)&h2,     g_h2);
    cudaGetSymbolAddress((void**)&qk2,    g_qk2);
    cudaGetSymbolAddress((void**)&bqq,    g_bqq);
    cudaGetSymbolAddress((void**)&blq,    g_blq);
    cudaGetSymbolAddress((void**)&bkq,    g_bkq);
    cudaGetSymbolAddress((void**)&blk,    g_blk);
    cudaGetSymbolAddress((void**)&attn,   g_attn);
    cudaGetSymbolAddress((void**)&gate,   g_gate);
    cudaGetSymbolAddress((void**)&o1,     g_o1);
    cudaGetSymbolAddress((void**)&lkvu,   g_lkvu);
    cudaGetSymbolAddress((void**)&lkvup,  g_lkvup);
    cudaGetSymbolAddress((void**)&wcat,   g_wcat);
    cudaGetSymbolAddress((void**)&bcat,   g_bcat);
    cudaGetSymbolAddress((void**)&ps,     g_ps);
    cudaGetSymbolAddress((void**)&ps2,    g_ps2);
    cudaGetSymbolAddress((void**)&stats,  g_stats);

    transpose_in_k<<<dim3(S_/32, D_/32, B_), dim3(32, 8)>>>(x, hstate);

    for (int l = 0; l < 2; l++) {
        const float* Wh = W_hid  + (size_t)l*D_*H_;
        const float* bh = b_hid  + l*H_;
        const float* kh = k_hid  + (size_t)l*H_*KS_;
        const float* Wq = W_qkp  + (size_t)l*D_*QK_;
        const float* bq = b_qkp  + l*QK_;
        const float* kq = k_qkp  + (size_t)l*QK_*KS_;
        const float* Wo = W_outp + (size_t)l*2*D_*D_;
        const float* bo = b_outp + l*D_;
        const float* ko = k_outp + (size_t)l*D_*KS_;
        const float* gm = gamma  + l*4*QK_;
        const float* bt = beta   + l*4*QK_;

        // merged [Wh*g | Wq*g] + [bh|bq]
        wcat_k<<<(D_*NCAT + 255)/256, 256>>>(Wh, Wq, bh, bq, g_hid + l, g_qkp + l, wcat, bcat);

        // nx (token shift) + scalenorm
        buildnx_k<<<BS_, 128>>>(hstate, nxn);

        // hq = silu(nxn @ [Wh*g|Wq*g] + [bh|bq])   [16384,2176,512]
        tgemm_k<1,false,false,false><<<dim3(NCAT/TBN, BS_/TBM, 1), 256>>>(
            nxn, wcat, hq, bcat, nullptr, 1.f,
            BS_, NCAT, D_, D_, NCAT, NCAT, 0, 0, 0, 1);

        // h2 = h1 + dwconv(h1)   (h1 = hq[:, :2048], stride NCAT)
        dwconv_k<<<dim3(H_/32, S_/64, B_), 256>>>(hq, kh, h2, nullptr, H_, NCAT, 0);
        // qk2 = qk1 + dwconv(qk1)  (qk1 = hq[:, 2048:], stride NCAT)
        dwconv_k<<<dim3(QK_/32, S_/64, B_), 256>>>(hq + H_, kq, qk2, nullptr, QK_, NCAT, 0);
        rotary_k<<<BS_, 128>>>(qk2, gm, bt, bqq, blq, bkq, blk);

        // attn = relu(qq@qk^T / 256)^2       batched 64 x [256,256,128]
        tgemm_k<2,false,true,false><<<dim3(GSZ_/TBN, GSZ_/TBM, B_*NGRP), 256>>>(
            bqq, bkq, attn, nullptr, nullptr, 1.f/(float)GSZ_,
            GSZ_, GSZ_, QK_, QK_, QK_, GSZ_,
            (long long)GSZ_*QK_, (long long)GSZ_*QK_, (long long)GSZ_*GSZ_, 1);

        // qvu = attn @ h2_group              batched 64 x [256,2048,256]
        tgemm_k<0,false,false,false><<<dim3(H_/TBN, GSZ_/TBM, B_*NGRP), 256>>>(
            attn, h2, h1, nullptr, nullptr, 1.f,
            GSZ_, H_, GSZ_, GSZ_, H_, H_,
            (long long)GSZ_*GSZ_, (long long)GSZ_*H_, (long long)GSZ_*H_, 1);

        // lkvu partials = lk^T @ h2 / S      split-K=8, batch 2 -> z=16
        tgemm_k<0,true,false,false><<<dim3(H_/TBN, QK_/TBM, B_*NSPLIT), 256>>>(
            blk, h2, lkvup, nullptr, nullptr, 1.f/(float)S_,
            QK_, H_, S_/NSPLIT, QK_, H_, H_,
            (long long)S_*QK_, (long long)S_*H_, (long long)QK_*H_, NSPLIT);
        lkvured_k<<<(B_*QK_*H_)/256, 256>>>(lkvup, lkvu);

        // qvu += lq @ lkvu                   batch 2 x [8192,2048,128]
        tgemm_k<0,false,false,true><<<dim3(H_/TBN, S_/TBM, B_), 256>>>(
            blq, lkvu, h1, nullptr, nullptr, 1.f,
            S_, H_, QK_, QK_, H_, H_,
            (long long)S_*QK_, (long long)QK_*H_, (long long)S_*H_, 1);

        // gated output + scalenorm (g_out folded)
        gating_k<<<BS_, 256>>>(h1, h2, g_outp + l, gate);

        // o1 = silu(gate @ Wo + bo)          [16384,512,1024]
        tgemm_k<1,false,false,false><<<dim3(D_/TBN, BS_/TBM, 1), 256>>>(
            gate, Wo, o1, bo, nullptr, 1.f,
            BS_, D_, 2*D_, 2*D_, D_, D_, 0, 0, 0, 1);

        // hstate += o1 + dwconv(o1)
        dwconv_k<<<dim3(D_/32, S_/64, B_), 256>>>(o1, ko, nullptr, hstate, D_, D_, 1);
    }

    ln_k<<<BS_, 128>>>(hstate, ln_g, ln_b, nxn, ps, ps2);
    gnred_k<<<B_, 256>>>(ps, ps2, stats);
    gnapply_k<<<dim3(S_/32, D_/32, B_), dim3(32, 8)>>>(nxn, stats, gn_w, gn_b, x, out);
}